// round 6
// baseline (speedup 1.0000x reference)
#include <cuda_runtime.h>
#include <cuda_bf16.h>
#include <math.h>

#define BB   1024
#define TT   64
#define NTOK (BB*TT)
#define PACKB 96

typedef unsigned int u32;

__device__ float g_xbuf[NTOK * 24];

__device__ __align__(16) __nv_bfloat16 g_w1_hi[256 * 40];
__device__ __align__(16) __nv_bfloat16 g_w1_lo[256 * 40];
__device__ __align__(16) __nv_bfloat16 g_w2_hi[4 * 256 * 72];
__device__ __align__(16) __nv_bfloat16 g_w2_lo[4 * 256 * 72];

__device__ __forceinline__ u32 smem_u32(const void* p) {
    u32 a;
    asm("{ .reg .u64 t; cvta.to.shared.u64 t, %1; cvt.u32.u64 %0, t; }" : "=r"(a) : "l"(p));
    return a;
}
__device__ __forceinline__ void ldsm_x4(u32* r, u32 addr) {
    asm volatile("ldmatrix.sync.aligned.m8n8.x4.shared.b16 {%0,%1,%2,%3}, [%4];"
                 : "=r"(r[0]), "=r"(r[1]), "=r"(r[2]), "=r"(r[3]) : "r"(addr));
}
__device__ __forceinline__ void mma16816(float* d, const u32* a, u32 b0, u32 b1) {
    asm volatile(
        "mma.sync.aligned.m16n8k16.row.col.f32.bf16.bf16.f32 "
        "{%0,%1,%2,%3}, {%4,%5,%6,%7}, {%8,%9}, {%0,%1,%2,%3};"
        : "+f"(d[0]), "+f"(d[1]), "+f"(d[2]), "+f"(d[3])
        : "r"(a[0]), "r"(a[1]), "r"(a[2]), "r"(a[3]), "r"(b0), "r"(b1));
}
__device__ __forceinline__ u32 pack_hi(float a, float b, float& ra, float& rb) {
    const __nv_bfloat16 ha = __float2bfloat16(a);
    const __nv_bfloat16 hb = __float2bfloat16(b);
    ra = a - __bfloat162float(ha);
    rb = b - __bfloat162float(hb);
    return (u32)__bfloat16_as_ushort(ha) | ((u32)__bfloat16_as_ushort(hb) << 16);
}
__device__ __forceinline__ u32 pack_bf(float a, float b) {
    return (u32)__bfloat16_as_ushort(__float2bfloat16(a)) |
           ((u32)__bfloat16_as_ushort(__float2bfloat16(b)) << 16);
}
__device__ __forceinline__ float ftanh(float x) {
    float y;
    asm("tanh.approx.f32 %0, %1;" : "=f"(y) : "f"(x));
    return y;
}
// fast e^x on the FMA/ALU pipes (no MUFU). valid for x <= 0 (softmax), clamped.
__device__ __forceinline__ float fexp(float x) {
    float y = fmaxf(x * 1.4426950408889634f, -120.f);
    const float t = y + 12582912.f;
    const int   i = __float_as_int(t) - 0x4B400000;
    const float f = y - (t - 12582912.f);
    float p = 1.3333558146e-3f;
    p = fmaf(p, f, 9.6181291076e-3f);
    p = fmaf(p, f, 5.5504108664e-2f);
    p = fmaf(p, f, 2.4022650696e-1f);
    p = fmaf(p, f, 6.9314718056e-1f);
    p = fmaf(p, f, 1.f);
    return __int_as_float(__float_as_int(p) + (i << 23));
}

// =====================================================================
// Kernel A: attention (blocks < BB) + weight pack (blocks >= BB)
// =====================================================================
__global__ __launch_bounds__(256) void attn_pack_kernel(
    const float* __restrict__ state,
    const float* __restrict__ Wq, const float* __restrict__ Wk, const float* __restrict__ Wv,
    const float* __restrict__ W1, const float* __restrict__ W2)
{
    __shared__ float s_state[TT][9];
    __shared__ float s_cs[TT][2];
    __shared__ float s_A[8][15];
    __shared__ float s_qk[TT][16];
    __shared__ float s_wv[80];
    __shared__ float s_wf[8][16];

    const int tid  = threadIdx.x;
    const int b    = blockIdx.x;

    if (b >= BB) {
        // ---- pack path ----
        const int base = (b - BB) * 256 + tid;
        for (int idx = base; idx < 4 * 256 * 72; idx += PACKB * 256) {
            const int c = idx / 18432, r = idx % 18432;
            const int n = r / 72, kl = r % 72;
            const float w = (kl < 64) ? W2[(c * 64 + kl) * 256 + n] : 0.f;
            const __nv_bfloat16 hi = __float2bfloat16(w);
            g_w2_hi[idx] = hi;
            g_w2_lo[idx] = __float2bfloat16(w - __bfloat162float(hi));
        }
        for (int idx = base; idx < 256 * 40; idx += PACKB * 256) {
            const int n = idx / 40, k = idx % 40;
            const float w = (k < 23) ? W1[k * 256 + n] : 0.f;
            const __nv_bfloat16 hi = __float2bfloat16(w);
            g_w1_hi[idx] = hi;
            g_w1_lo[idx] = __float2bfloat16(w - __bfloat162float(hi));
        }
        return;
    }

    const int warp = tid >> 5;
    const int lane = tid & 31;

    const float* srow = state + (size_t)b * TT * 8;
    for (int i = tid; i < TT * 8; i += 256) s_state[i >> 3][i & 7] = srow[i];
    if (tid < 75) s_wv[tid] = Wv[tid];
    if (tid < 120) {
        const int i = tid / 15, hf = tid % 15;
        const int h = hf / 5, ff = hf % 5;
        float a = 0.f;
        #pragma unroll
        for (int k = 0; k < 5; ++k)
            a = fmaf(Wq[i * 15 + h * 5 + k], Wk[ff * 15 + h * 5 + k], a);
        s_A[i][hf] = a;
    }
    __syncthreads();
    if (tid < TT) {
        float ang = -s_state[tid][7] + 1.5707963267948966f;
        float s_, c_;
        __sincosf(ang, &s_, &c_);
        s_cs[tid][0] = c_; s_cs[tid][1] = s_;
    }
    for (int item = tid; item < TT * 15; item += 256) {
        const int t = item / 15, hf = item % 15;
        float a = 0.f;
        #pragma unroll
        for (int i = 0; i < 8; ++i) a = fmaf(s_state[t][i], s_A[i][hf], a);
        s_qk[t][hf] = a;
    }
    __syncthreads();

    const float INV_SQRT5 = 0.44721359549995793f;

    #pragma unroll 1
    for (int pass = 0; pass < 8; ++pass) {
        const int t = pass * 8 + warp;

        float f0[5], f1[5];
        float sc[2][3];
        #pragma unroll
        for (int p = 0; p < 2; ++p) {
            const int n = lane + 32 * p;
            const bool valid = (n < 63);
            const int nn = valid ? n : 0;
            const int j  = (nn < t) ? nn : nn + 1;

            const float c_ = s_cs[j][0];
            const float s_ = s_cs[j][1];
            const float dx0 = s_state[j][0] - s_state[t][0];
            const float dy0 = s_state[j][1] - s_state[t][1];
            const float dx1 = s_state[j][2] - s_state[t][2];
            const float dy1 = s_state[j][3] - s_state[t][3];
            const float xn0 = dx0 * c_ - dy0 * s_;
            const float yn0 = dx0 * s_ + dy0 * c_;
            const float xn1 = dx1 * c_ - dy1 * s_;
            const float yn1 = dx1 * s_ + dy1 * c_;
            const float r2   = fmaf(xn0, xn0, yn0 * yn0);
            const float rinv = rsqrtf(r2);
            const float r    = r2 * rinv;
            // sigmoid(2-5r) = 0.5 + 0.5*tanh(1-2.5r)  (one MUFU.TANH)
            const float rt   = fmaf(0.5f, ftanh(fmaf(-2.5f, r, 1.f)), 0.5f);
            float f[5];
            f[0] = valid ? xn0 * rinv : 0.f;
            f[1] = valid ? yn0 * rinv : 0.f;
            f[2] = valid ? xn1 : 0.f;
            f[3] = valid ? yn1 : 0.f;
            f[4] = valid ? rt  : 0.f;
            #pragma unroll
            for (int ff = 0; ff < 5; ++ff) { if (p == 0) f0[ff] = f[ff]; else f1[ff] = f[ff]; }

            #pragma unroll
            for (int h = 0; h < 3; ++h) {
                float d = 0.f;
                #pragma unroll
                for (int ff = 0; ff < 5; ++ff) d = fmaf(f[ff], s_qk[t][h * 5 + ff], d);
                sc[p][h] = valid ? d * INV_SQRT5 : -1e30f;
            }
        }

        float w01[2][3];
        #pragma unroll
        for (int h = 0; h < 3; ++h) {
            float m = fmaxf(sc[0][h], sc[1][h]);
            #pragma unroll
            for (int off = 16; off > 0; off >>= 1)
                m = fmaxf(m, __shfl_xor_sync(0xffffffffu, m, off));
            float e0 = fexp(sc[0][h] - m);
            float e1 = fexp(sc[1][h] - m);
            float s  = e0 + e1;
            #pragma unroll
            for (int off = 16; off > 0; off >>= 1)
                s += __shfl_xor_sync(0xffffffffu, s, off);
            const float si = __fdividef(1.f, s);
            w01[0][h] = e0 * si;
            w01[1][h] = e1 * si;
        }

        float wf[15];
        #pragma unroll
        for (int h = 0; h < 3; ++h)
            #pragma unroll
            for (int ff = 0; ff < 5; ++ff)
                wf[h * 5 + ff] = fmaf(w01[0][h], f0[ff], w01[1][h] * f1[ff]);
        #pragma unroll
        for (int i = 0; i < 15; ++i)
            #pragma unroll
            for (int off = 16; off > 0; off >>= 1)
                wf[i] += __shfl_xor_sync(0xffffffffu, wf[i], off);

        if (lane == 0) {
            #pragma unroll
            for (int i = 0; i < 15; ++i) s_wf[warp][i] = wf[i];
        }
        __syncwarp();

        const size_t g = (size_t)b * TT + t;
        if (lane < 15) {
            const int h = lane / 5;
            float a = 0.f;
            #pragma unroll
            for (int ff = 0; ff < 5; ++ff)
                a = fmaf(s_wf[warp][h * 5 + ff], s_wv[ff * 15 + lane], a);
            g_xbuf[g * 24 + lane] = a;
        } else if (lane < 23) {
            g_xbuf[g * 24 + lane] = s_state[t][lane - 15];
        }
    }
}

// =====================================================================
// Kernel B: HMMA MLP + heads. 128 tokens/block, 256 threads (8 warps).
// =====================================================================
#define OFF_B1   0
#define OFF_B2   1024
#define OFF_WMU  2048
#define OFF_WLS  4096
#define OFF_WBUF 6144
#define W2LO_OFF 36864
#define W1LO_OFF 20480
#define A1HI_OFF 40960
#define A1LO_OFF 51200
#define OFF_A2H  79872
#define A2LO_OFF 67584
#define SMEM_TOT 215040

__global__ __launch_bounds__(256) void mlp_kernel(
    const float* __restrict__ noise,
    const float* __restrict__ b1g, const float* __restrict__ b2g,
    const float* __restrict__ Wmu, const float* __restrict__ bmu,
    const float* __restrict__ Wls, const float* __restrict__ bls,
    float* __restrict__ out)
{
    extern __shared__ __align__(16) unsigned char smem[];
    const u32 sb  = smem_u32(smem);
    const int tid = threadIdx.x;
    const int wid = tid >> 5;
    const int lane = tid & 31;
    const int tg  = lane & 3;
    const int gid = lane >> 2;

    float* s_b1  = (float*)(smem + OFF_B1);
    float* s_b2  = (float*)(smem + OFF_B2);
    float* s_wmu = (float*)(smem + OFF_WMU);
    float* s_wls = (float*)(smem + OFF_WLS);

    s_b1[tid] = b1g[tid];
    s_b2[tid] = b2g[tid];
    s_wmu[tid] = Wmu[tid]; s_wmu[tid + 256] = Wmu[tid + 256];
    s_wls[tid] = Wls[tid]; s_wls[tid + 256] = Wls[tid + 256];

    if (tid < 128) {
        const size_t tok = (size_t)blockIdx.x * 128 + tid;
        float x[24];
        const float4* xp = (const float4*)(g_xbuf + tok * 24);
        #pragma unroll
        for (int i = 0; i < 6; ++i) ((float4*)x)[i] = xp[i];
        x[23] = 0.f;
        u32* dh = (u32*)(smem + OFF_WBUF + A1HI_OFF + tid * 80);
        u32* dl = (u32*)(smem + OFF_WBUF + A1LO_OFF + tid * 80);
        #pragma unroll
        for (int i = 0; i < 16; ++i) {
            if (i < 12) {
                float ra, rb;
                dh[i] = pack_hi(x[2 * i], x[2 * i + 1], ra, rb);
                dl[i] = pack_bf(ra, rb);
            } else { dh[i] = 0u; dl[i] = 0u; }
        }
    }
    {
        const uint4* s1 = (const uint4*)g_w1_hi;
        const uint4* s2 = (const uint4*)g_w1_lo;
        uint4* d1 = (uint4*)(smem + OFF_WBUF);
        uint4* d2 = (uint4*)(smem + OFF_WBUF + W1LO_OFF);
        #pragma unroll
        for (int i = 0; i < 5; ++i) { d1[tid + 256 * i] = s1[tid + 256 * i]; d2[tid + 256 * i] = s2[tid + 256 * i]; }
    }
    __syncthreads();

    float acc[32][4];
    #pragma unroll
    for (int j = 0; j < 32; ++j)
        #pragma unroll
        for (int c = 0; c < 4; ++c) acc[j][c] = 0.f;

    const u32 aRowB = (u32)(wid * 16 + (lane & 15));
    const u32 aColB = (u32)(lane & 16);
    const u32 bRow  = (u32)((lane & 7) + ((lane >> 4) << 3));
    const u32 bKB   = (u32)((lane & 8) << 1);

    // ---- layer 1: K=32 ----
    {
        const u32 aH = sb + OFF_WBUF + A1HI_OFF + aRowB * 80 + aColB;
        const u32 aL = sb + OFF_WBUF + A1LO_OFF + aRowB * 80 + aColB;
        const u32 bH = sb + OFF_WBUF + bRow * 80 + bKB;
        const u32 bL = bH + W1LO_OFF;
        #pragma unroll
        for (int ks = 0; ks < 2; ++ks) {
            u32 ah[4], al[4];
            ldsm_x4(ah, aH + ks * 32);
            ldsm_x4(al, aL + ks * 32);
            #pragma unroll
            for (int jp = 0; jp < 16; ++jp) {
                u32 bh[4], bl[4];
                ldsm_x4(bh, bH + jp * 1280 + ks * 32);
                ldsm_x4(bl, bL + jp * 1280 + ks * 32);
                mma16816(acc[2 * jp], ah, bh[0], bh[1]);
                mma16816(acc[2 * jp], al, bh[0], bh[1]);
                mma16816(acc[2 * jp], ah, bl[0], bl[1]);
                mma16816(acc[2 * jp + 1], ah, bh[2], bh[3]);
                mma16816(acc[2 * jp + 1], al, bh[2], bh[3]);
                mma16816(acc[2 * jp + 1], ah, bl[2], bl[3]);
            }
        }
    }

    // ---- h1 = relu(acc+b1) -> A2 ----
    {
        const int r0 = wid * 16 + gid, r1 = r0 + 8;
        #pragma unroll
        for (int j = 0; j < 32; ++j) {
            const int n0 = j * 8 + tg * 2;
            const float ba = s_b1[n0], bb = s_b1[n0 + 1];
            const float h00 = fmaxf(acc[j][0] + ba, 0.f);
            const float h01 = fmaxf(acc[j][1] + bb, 0.f);
            const float h10 = fmaxf(acc[j][2] + ba, 0.f);
            const float h11 = fmaxf(acc[j][3] + bb, 0.f);
            float ra, rb;
            u32 v = pack_hi(h00, h01, ra, rb);
            *(u32*)(smem + OFF_A2H + r0 * 528 + n0 * 2) = v;
            *(u32*)(smem + OFF_A2H + A2LO_OFF + r0 * 528 + n0 * 2) = pack_bf(ra, rb);
            v = pack_hi(h10, h11, ra, rb);
            *(u32*)(smem + OFF_A2H + r1 * 528 + n0 * 2) = v;
            *(u32*)(smem + OFF_A2H + A2LO_OFF + r1 * 528 + n0 * 2) = pack_bf(ra, rb);
            acc[j][0] = 0.f; acc[j][1] = 0.f; acc[j][2] = 0.f; acc[j][3] = 0.f;
        }
    }

    // ---- layer 2: K=256 in 4 chunks ----
    const u32 a2H = sb + OFF_A2H + aRowB * 528 + aColB;
    const u32 a2L = a2H + A2LO_OFF;
    const u32 b2H = sb + OFF_WBUF + bRow * 144 + bKB;
    const u32 b2L = b2H + W2LO_OFF;

    #pragma unroll 1
    for (int kc = 0; kc < 4; ++kc) {
        __syncthreads();
        {
            const uint4* s1 = (const uint4*)(g_w2_hi + kc * 18432);
            const uint4* s2 = (const uint4*)(g_w2_lo + kc * 18432);
            uint4* d1 = (uint4*)(smem + OFF_WBUF);
            uint4* d2 = (uint4*)(smem + OFF_WBUF + W2LO_OFF);
            #pragma unroll
            for (int i = 0; i < 9; ++i) { d1[tid + 256 * i] = s1[tid + 256 * i]; d2[tid + 256 * i] = s2[tid + 256 * i]; }
        }
        __syncthreads();

        #pragma unroll
        for (int ks = 0; ks < 4; ++ks) {
            u32 ah[4], al[4];
            ldsm_x4(ah, a2H + kc * 128 + ks * 32);
            ldsm_x4(al, a2L + kc * 128 + ks * 32);
            #pragma unroll
            for (int jp = 0; jp < 16; ++jp) {
                u32 bh[4], bl[4];
                ldsm_x4(bh, b2H + jp * 2304 + ks * 32);
                ldsm_x4(bl, b2L + jp * 2304 + ks * 32);
                mma16816(acc[2 * jp], ah, bh[0], bh[1]);
                mma16816(acc[2 * jp], al, bh[0], bh[1]);
                mma16816(acc[2 * jp], ah, bl[0], bl[1]);
                mma16816(acc[2 * jp + 1], ah, bh[2], bh[3]);
                mma16816(acc[2 * jp + 1], al, bh[2], bh[3]);
                mma16816(acc[2 * jp + 1], ah, bl[2], bl[3]);
            }
        }
    }

    // ---- epilogue ----
    float p00 = 0.f, p01 = 0.f, p02 = 0.f, p03 = 0.f;
    float p10 = 0.f, p11 = 0.f, p12 = 0.f, p13 = 0.f;
    #pragma unroll
    for (int j = 0; j < 32; ++j) {
        const int n0 = j * 8 + tg * 2;
        const float ba = s_b2[n0], bb = s_b2[n0 + 1];
        const float h00 = fmaxf(acc[j][0] + ba, 0.f);
        const float h01 = fmaxf(acc[j][1] + bb, 0.f);
        const float h10 = fmaxf(acc[j][2] + ba, 0.f);
        const float h11 = fmaxf(acc[j][3] + bb, 0.f);
        const float m0a = s_wmu[n0 * 2 + 0], m1a = s_wmu[n0 * 2 + 1];
        const float m0b = s_wmu[n0 * 2 + 2], m1b = s_wmu[n0 * 2 + 3];
        const float l0a = s_wls[n0 * 2 + 0], l1a = s_wls[n0 * 2 + 1];
        const float l0b = s_wls[n0 * 2 + 2], l1b = s_wls[n0 * 2 + 3];
        p00 = fmaf(h00, m0a, fmaf(h01, m0b, p00));
        p01 = fmaf(h00, m1a, fmaf(h01, m1b, p01));
        p02 = fmaf(h00, l0a, fmaf(h01, l0b, p02));
        p03 = fmaf(h00, l1a, fmaf(h01, l1b, p03));
        p10 = fmaf(h10, m0a, fmaf(h11, m0b, p10));
        p11 = fmaf(h10, m1a, fmaf(h11, m1b, p11));
        p12 = fmaf(h10, l0a, fmaf(h11, l0b, p12));
        p13 = fmaf(h10, l1a, fmaf(h11, l1b, p13));
    }
    #pragma unroll
    for (int off = 1; off <= 2; off <<= 1) {
        p00 += __shfl_xor_sync(0xffffffffu, p00, off);
        p01 += __shfl_xor_sync(0xffffffffu, p01, off);
        p02 += __shfl_xor_sync(0xffffffffu, p02, off);
        p03 += __shfl_xor_sync(0xffffffffu, p03, off);
        p10 += __shfl_xor_sync(0xffffffffu, p10, off);
        p11 += __shfl_xor_sync(0xffffffffu, p11, off);
        p12 += __shfl_xor_sync(0xffffffffu, p12, off);
        p13 += __shfl_xor_sync(0xffffffffu, p13, off);
    }

    if (tg == 0) {
        const float bm0 = bmu[0], bm1 = bmu[1];
        const float bl0 = bls[0], bl1 = bls[1];
        const float HL2PI = 0.9189385332046727f;
        #pragma unroll
        for (int rr = 0; rr < 2; ++rr) {
            const size_t g = (size_t)blockIdx.x * 128 + wid * 16 + gid + rr * 8;
            const float q0 = rr ? p10 : p00;
            const float q1 = rr ? p11 : p01;
            const float q2 = rr ? p12 : p02;
            const float q3 = rr ? p13 : p03;
            const float mu0 = ftanh(q0 + bm0);
            const float mu1 = ftanh(q1 + bm1);
            const float t0  = ftanh(q2 + bl0);
            const float t1  = ftanh(q3 + bl1);
            const float ls0 = -20.f + 11.f * (t0 + 1.f);
            const float ls1 = -20.f + 11.f * (t1 + 1.f);
            const float sd0 = __expf(ls0), sd1 = __expf(ls1);
            const float n0 = noise[g * 2 + 0], n1 = noise[g * 2 + 1];
            const float z0 = mu0 + sd0 * n0, z1 = mu1 + sd1 * n1;
            const float a0 = ftanh(z0), a1 = ftanh(z1);
            const float lp0 = -0.5f * n0 * n0 - ls0 - HL2PI - __logf(1.f - a0 * a0 + 1e-7f);
            const float lp1 = -0.5f * n1 * n1 - ls1 - HL2PI - __logf(1.f - a1 * a1 + 1e-7f);
            out[g * 2 + 0] = a0;
            out[g * 2 + 1] = a1;
            out[(size_t)NTOK * 2 + g] = lp0 + lp1;
        }
    }
}

extern "C" void kernel_launch(void* const* d_in, const int* in_sizes, int n_in,
                              void* d_out, int out_size) {
    const float* state = (const float*)d_in[0];
    const float* noise = (const float*)d_in[1];
    const float* Wq    = (const float*)d_in[2];
    const float* Wk    = (const float*)d_in[3];
    const float* Wv    = (const float*)d_in[4];
    const float* W1    = (const float*)d_in[5];
    const float* b1    = (const float*)d_in[6];
    const float* W2    = (const float*)d_in[7];
    const float* b2    = (const float*)d_in[8];
    const float* Wmu   = (const float*)d_in[9];
    const float* bmu   = (const float*)d_in[10];
    const float* Wls   = (const float*)d_in[11];
    const float* bls   = (const float*)d_in[12];

    cudaFuncSetAttribute(mlp_kernel, cudaFuncAttributeMaxDynamicSharedMemorySize, SMEM_TOT);

    attn_pack_kernel<<<BB + PACKB, 256>>>(state, Wq, Wk, Wv, W1, W2);
    mlp_kernel<<<NTOK / 128, 256, SMEM_TOT>>>(noise, b1, b2, Wmu, bmu, Wls, bls,
                                              (float*)d_out);
}